// round 1
// baseline (speedup 1.0000x reference)
#include <cuda_runtime.h>
#include <cuda_bf16.h>

// Shapes (fixed per reference)
#define NROI 1024
#define SSZ  14
#define CCH  256
#define M_TOT (NROI * SSZ * SSZ)   // 200704 pixels in the 14x14 grid

// Ping-pong activation buffers (device globals: allocation-free per harness rules)
__device__ float g_buf0[NROI * SSZ * SSZ * CCH];
__device__ float g_buf1[NROI * SSZ * SSZ * CCH];

// ---------------------------------------------------------------------------
// Conv 3x3 SAME, C=256 -> 256, + bias + ReLU.  Implicit GEMM:
//   M = 200704 (n,h,w), N = 256 (co), K = 2304 ((kh*3+kw)*256 + ci)
// BM=128, BN=128, BK=16, 256 threads, 8x8 accum per thread.
// ---------------------------------------------------------------------------
__global__ __launch_bounds__(256)
void conv3x3_relu_kernel(const float* __restrict__ in,
                         const float* __restrict__ W,     // [3,3,256,256]
                         const float* __restrict__ bias,  // [256]
                         float* __restrict__ out)
{
    __shared__ float As[16][128];
    __shared__ float Bs[16][128];

    const int t  = threadIdx.x;
    const int m0 = blockIdx.x * 128;
    const int n0 = blockIdx.y * 128;

    // A-load mapping: 512 float4 per stage, 2 per thread
    const int rA = t >> 2;            // row-in-tile 0..63 (and +64)
    const int c4 = (t & 3) * 4;       // k-sub offset {0,4,8,12}
    int rn[2], rh[2], rw[2];
#pragma unroll
    for (int j = 0; j < 2; ++j) {
        int m = m0 + rA + j * 64;
        int n = m / 196;
        int p = m - n * 196;
        int h = p / 14;
        rn[j] = n; rh[j] = h; rw[j] = p - h * 14;
    }
    // B-load mapping: 512 float4 per stage, 2 per thread
    const int krB = t >> 5;           // 0..7 (and +8)
    const int cbB = (t & 31) * 4;

    const int ty = t >> 4;            // 0..15 -> rows ty*8..
    const int tx = t & 15;            // 0..15 -> cols tx*8..

    float acc[8][8];
#pragma unroll
    for (int i = 0; i < 8; ++i)
#pragma unroll
        for (int j = 0; j < 8; ++j) acc[i][j] = 0.f;

    for (int kc = 0; kc < 144; ++kc) {
        const int kq  = kc >> 4;                 // kh*3+kw (0..8)
        const int kh  = kq / 3;
        const int kw  = kq - kh * 3;
        const int cib = (kc & 15) << 4;          // ci base 0..240

        // ---- load A tile (im2col gather, zero-padded SAME) ----
#pragma unroll
        for (int j = 0; j < 2; ++j) {
            int ih = rh[j] + kh - 1;
            int iw = rw[j] + kw - 1;
            float4 v = make_float4(0.f, 0.f, 0.f, 0.f);
            if ((unsigned)ih < 14u && (unsigned)iw < 14u) {
                v = *(const float4*)&in[(((rn[j] * 14 + ih) * 14 + iw) << 8) + cib + c4];
            }
            int row = rA + j * 64;
            As[c4 + 0][row] = v.x;
            As[c4 + 1][row] = v.y;
            As[c4 + 2][row] = v.z;
            As[c4 + 3][row] = v.w;
        }
        // ---- load B tile (weights, fully coalesced) ----
#pragma unroll
        for (int j = 0; j < 2; ++j) {
            int kr = krB + j * 8;
            float4 v = *(const float4*)&W[((kq << 8) + cib + kr) * 256 + n0 + cbB];
            *(float4*)&Bs[kr][cbB] = v;
        }
        __syncthreads();

#pragma unroll
        for (int kk = 0; kk < 16; ++kk) {
            float a[8], b[8];
            *(float4*)&a[0] = *(const float4*)&As[kk][ty * 8];
            *(float4*)&a[4] = *(const float4*)&As[kk][ty * 8 + 4];
            *(float4*)&b[0] = *(const float4*)&Bs[kk][tx * 8];
            *(float4*)&b[4] = *(const float4*)&Bs[kk][tx * 8 + 4];
#pragma unroll
            for (int i = 0; i < 8; ++i)
#pragma unroll
                for (int j = 0; j < 8; ++j)
                    acc[i][j] += a[i] * b[j];
        }
        __syncthreads();
    }

    // ---- epilogue: bias + relu, vectorized store ----
    float bv[8];
#pragma unroll
    for (int j = 0; j < 8; ++j) bv[j] = bias[n0 + tx * 8 + j];

#pragma unroll
    for (int i = 0; i < 8; ++i) {
        int m = m0 + ty * 8 + i;
        float4 o0, o1;
        o0.x = fmaxf(acc[i][0] + bv[0], 0.f);
        o0.y = fmaxf(acc[i][1] + bv[1], 0.f);
        o0.z = fmaxf(acc[i][2] + bv[2], 0.f);
        o0.w = fmaxf(acc[i][3] + bv[3], 0.f);
        o1.x = fmaxf(acc[i][4] + bv[4], 0.f);
        o1.y = fmaxf(acc[i][5] + bv[5], 0.f);
        o1.z = fmaxf(acc[i][6] + bv[6], 0.f);
        o1.w = fmaxf(acc[i][7] + bv[7], 0.f);
        *(float4*)&out[(m << 8) + n0 + tx * 8]     = o0;
        *(float4*)&out[(m << 8) + n0 + tx * 8 + 4] = o1;
    }
}

// ---------------------------------------------------------------------------
// Fused: conv_transpose(2x2, stride 2, VALID) + bias + ReLU + 1x1 conv(+bm).
// Key fact: out[n, 2i+a, 2j+b, :] depends on exactly one input pixel (n,i,j),
// and JAX conv_transpose (transpose_kernel=False) uses Wt[1-a, 1-b].
// Grid: x over M=200704 pixel tiles (BM=64), y over the 4 (a,b) parities.
// Main GEMM: 64x256x256 (BN=256 covers all channels so the 1x1 mask GEMM can
// run as an in-CTA epilogue from smem -> no 822 MB intermediate in HBM).
// ---------------------------------------------------------------------------
#define ZPITCH 260   // 64 x 260 z-tile pitch (16B aligned, conflict-free)

__global__ __launch_bounds__(256)
void deconv_mask_kernel(const float* __restrict__ y,    // [1024,14,14,256]
                        const float* __restrict__ Wt,   // [2,2,256,256]
                        const float* __restrict__ bt,   // [256]
                        const float* __restrict__ Wm,   // [256,80] (1x1)
                        const float* __restrict__ bm,   // [80]
                        float* __restrict__ out)        // [1024,28,28,80]
{
    extern __shared__ float sm[];
    float* As  = sm;                    // [16][68]
    float* Bs  = As + 16 * 68;          // [16][256]
    float* zs  = Bs + 16 * 256;         // [64][ZPITCH]
    float* wms = zs + 64 * ZPITCH;      // [256][80]

    const int t  = threadIdx.x;
    const int m0 = blockIdx.x * 64;
    const int ab = blockIdx.y;          // (a,b) parity
    const int a  = ab >> 1, b = ab & 1;
    const float* wbase = Wt + (3 - ab) * 256 * 256;  // Wt[1-a,1-b]

    // stage Wm into smem (20480 floats)
    for (int i = t * 4; i < 256 * 80; i += 256 * 4)
        *(float4*)&wms[i] = *(const float4*)&Wm[i];

    const int rA = t >> 2;              // 0..63
    const int c4 = (t & 3) * 4;
    const int ty = t >> 5;              // warp id 0..7 -> rows ty*8..
    const int tx = t & 31;              // lane -> cols tx*8..

    float acc[8][8];
#pragma unroll
    for (int i = 0; i < 8; ++i)
#pragma unroll
        for (int j = 0; j < 8; ++j) acc[i][j] = 0.f;

    for (int kc = 0; kc < 16; ++kc) {
        // A: contiguous rows of y
        float4 av = *(const float4*)&y[((m0 + rA) << 8) + kc * 16 + c4];
        As[(c4 + 0) * 68 + rA] = av.x;
        As[(c4 + 1) * 68 + rA] = av.y;
        As[(c4 + 2) * 68 + rA] = av.z;
        As[(c4 + 3) * 68 + rA] = av.w;
        // B: 16x256 weight slab, 4 float4 per thread
#pragma unroll
        for (int j = 0; j < 4; ++j) {
            int v  = t + j * 256;
            int kr = v >> 6;            // 0..15
            int cb = (v & 63) * 4;
            *(float4*)&Bs[kr * 256 + cb] =
                *(const float4*)&wbase[(kc * 16 + kr) * 256 + cb];
        }
        __syncthreads();
#pragma unroll
        for (int kk = 0; kk < 16; ++kk) {
            float af[8], bf[8];
            *(float4*)&af[0] = *(const float4*)&As[kk * 68 + ty * 8];
            *(float4*)&af[4] = *(const float4*)&As[kk * 68 + ty * 8 + 4];
            *(float4*)&bf[0] = *(const float4*)&Bs[kk * 256 + tx * 8];
            *(float4*)&bf[4] = *(const float4*)&Bs[kk * 256 + tx * 8 + 4];
#pragma unroll
            for (int i = 0; i < 8; ++i)
#pragma unroll
                for (int j = 0; j < 8; ++j)
                    acc[i][j] += af[i] * bf[j];
        }
        __syncthreads();
    }

    // bias + relu -> z tile in smem
    float bvv[8];
#pragma unroll
    for (int j = 0; j < 8; ++j) bvv[j] = bt[tx * 8 + j];
#pragma unroll
    for (int i = 0; i < 8; ++i) {
        int r = ty * 8 + i;
        float4 z0, z1;
        z0.x = fmaxf(acc[i][0] + bvv[0], 0.f);
        z0.y = fmaxf(acc[i][1] + bvv[1], 0.f);
        z0.z = fmaxf(acc[i][2] + bvv[2], 0.f);
        z0.w = fmaxf(acc[i][3] + bvv[3], 0.f);
        z1.x = fmaxf(acc[i][4] + bvv[4], 0.f);
        z1.y = fmaxf(acc[i][5] + bvv[5], 0.f);
        z1.z = fmaxf(acc[i][6] + bvv[6], 0.f);
        z1.w = fmaxf(acc[i][7] + bvv[7], 0.f);
        *(float4*)&zs[r * ZPITCH + tx * 8]     = z0;
        *(float4*)&zs[r * ZPITCH + tx * 8 + 4] = z1;
    }
    __syncthreads();

    // ---- mask epilogue: out64x80 = relu_z(64x256) @ Wm(256x80) + bm ----
    // thread -> 4 rows x 5 classes
    const int rg = (t >> 4) * 4;        // row base
    const int cg = (t & 15) * 5;        // class base
    float oacc[4][5];
#pragma unroll
    for (int rr = 0; rr < 4; ++rr)
#pragma unroll
        for (int cc = 0; cc < 5; ++cc) oacc[rr][cc] = bm[cg + cc];

    for (int co = 0; co < 256; ++co) {
        float zv[4], wv[5];
#pragma unroll
        for (int rr = 0; rr < 4; ++rr) zv[rr] = zs[(rg + rr) * ZPITCH + co];
#pragma unroll
        for (int cc = 0; cc < 5; ++cc) wv[cc] = wms[co * 80 + cg + cc];
#pragma unroll
        for (int rr = 0; rr < 4; ++rr)
#pragma unroll
            for (int cc = 0; cc < 5; ++cc)
                oacc[rr][cc] += zv[rr] * wv[cc];
    }

#pragma unroll
    for (int rr = 0; rr < 4; ++rr) {
        int m  = m0 + rg + rr;
        int n  = m / 196;
        int p  = m - n * 196;
        int ii = p / 14;
        int jj = p - ii * 14;
        int oh = ii * 2 + a;
        int ow = jj * 2 + b;
        float* op = &out[((n * 28 + oh) * 28 + ow) * 80 + cg];
#pragma unroll
        for (int cc = 0; cc < 5; ++cc) op[cc] = oacc[rr][cc];
    }
}

// ---------------------------------------------------------------------------
extern "C" void kernel_launch(void* const* d_in, const int* in_sizes, int n_in,
                              void* d_out, int out_size)
{
    const float* x  = (const float*)d_in[0];  // [1024,14,14,256]
    const float* Wc = (const float*)d_in[1];  // [4,3,3,256,256]
    const float* bc = (const float*)d_in[2];  // [4,256]
    const float* Wt = (const float*)d_in[3];  // [2,2,256,256]
    const float* bt = (const float*)d_in[4];  // [256]
    const float* Wm = (const float*)d_in[5];  // [1,1,256,80]
    const float* bm = (const float*)d_in[6];  // [80]
    float* out = (float*)d_out;

    float *b0, *b1;
    cudaGetSymbolAddress((void**)&b0, g_buf0);
    cudaGetSymbolAddress((void**)&b1, g_buf1);

    const size_t smem_deconv =
        (16 * 68 + 16 * 256 + 64 * ZPITCH + 256 * 80) * sizeof(float); // ~169 KB
    cudaFuncSetAttribute(deconv_mask_kernel,
                         cudaFuncAttributeMaxDynamicSharedMemorySize,
                         (int)smem_deconv);

    dim3 cgrid(M_TOT / 128, 2);   // 1568 x 2
    const int WSTRIDE = 3 * 3 * 256 * 256;   // per-layer conv weights

    conv3x3_relu_kernel<<<cgrid, 256>>>(x,  Wc + 0 * WSTRIDE, bc + 0,   b0);
    conv3x3_relu_kernel<<<cgrid, 256>>>(b0, Wc + 1 * WSTRIDE, bc + 256, b1);
    conv3x3_relu_kernel<<<cgrid, 256>>>(b1, Wc + 2 * WSTRIDE, bc + 512, b0);
    conv3x3_relu_kernel<<<cgrid, 256>>>(b0, Wc + 3 * WSTRIDE, bc + 768, b1);

    dim3 dgrid(M_TOT / 64, 4);    // 3136 x 4 (pixel tiles x (a,b) parity)
    deconv_mask_kernel<<<dgrid, 256, smem_deconv>>>(b1, Wt, bt, Wm, bm, out);
}

// round 5
// speedup vs baseline: 1.7569x; 1.7569x over previous
#include <cuda_runtime.h>
#include <cstdint>

#define NROI 1024
#define M_TOT (NROI * 196)          // 200704
#define KTOT  2304
#define WLSTRIDE (256 * KTOT)

// Device-global scratch (allocation-free per harness rules)
__device__ float g_buf0[M_TOT * 256];
__device__ float g_buf1[M_TOT * 256];
__device__ float g_wT[4 * 256 * KTOT];   // [layer][co][k], k=(kh*3+kw)*256+ci, tf32-rounded

// ---------------------------------------------------------------------------
__device__ __forceinline__ uint32_t smem_u32(const void* p) {
    uint32_t a;
    asm("{ .reg .u64 t; cvta.to.shared.u64 t, %1; cvt.u32.u64 %0, t; }"
        : "=r"(a) : "l"(p));
    return a;
}
__device__ __forceinline__ float tf32r(float x) {
    float o; asm("cvt.rna.tf32.f32 %0, %1;" : "=f"(o) : "f"(x)); return o;
}
__device__ __forceinline__ void cp16(uint32_t dst, const void* src, uint32_t bytes) {
    asm volatile("cp.async.cg.shared.global [%0], [%1], 16, %2;"
                 :: "r"(dst), "l"(src), "r"(bytes) : "memory");
}
__device__ __forceinline__ void mma_tf32(float c[4], const uint32_t a[4],
                                         const uint32_t b[2]) {
    asm volatile(
        "mma.sync.aligned.m16n8k8.row.col.f32.tf32.tf32.f32 "
        "{%0,%1,%2,%3}, {%4,%5,%6,%7}, {%8,%9}, {%0,%1,%2,%3};"
        : "+f"(c[0]), "+f"(c[1]), "+f"(c[2]), "+f"(c[3])
        : "r"(a[0]), "r"(a[1]), "r"(a[2]), "r"(a[3]), "r"(b[0]), "r"(b[1]));
}

// ---------------------------------------------------------------------------
// Round input activations to tf32 (removes in-loop cvt and truncation bias)
// ---------------------------------------------------------------------------
__global__ __launch_bounds__(256)
void round_tf32_kernel(const float* __restrict__ in, float* __restrict__ out)
{
    int i = (blockIdx.x * 256 + threadIdx.x) * 4;
    float4 v = *(const float4*)(in + i);
    v.x = tf32r(v.x); v.y = tf32r(v.y); v.z = tf32r(v.z); v.w = tf32r(v.w);
    *(float4*)(out + i) = v;
}

// ---------------------------------------------------------------------------
// Weight transpose: Wc[l][kq][ci][co] -> g_wT[l][co][kq*256+ci], tf32-rounded
// ---------------------------------------------------------------------------
__global__ __launch_bounds__(256)
void transpose_w(const float* __restrict__ Wc, float* __restrict__ wT)
{
    __shared__ float ts[32][33];
    const int l  = blockIdx.z;
    const int kq = blockIdx.y;
    const int ci0 = (blockIdx.x >> 3) * 32;
    const int co0 = (blockIdx.x & 7) * 32;
    const int tx = threadIdx.x & 31, ty = threadIdx.x >> 5;
#pragma unroll
    for (int i = ty; i < 32; i += 8)
        ts[i][tx] = tf32r(Wc[((l * 9 + kq) * 256 + ci0 + i) * 256 + co0 + tx]);
    __syncthreads();
#pragma unroll
    for (int i = ty; i < 32; i += 8)
        wT[(l * 256 + co0 + i) * KTOT + kq * 256 + ci0 + tx] = ts[tx][i];
}

// ---------------------------------------------------------------------------
// Conv 3x3 SAME (256->256) + bias + ReLU via mma.sync tf32.
// BM=128 BN=128 BK=32, 8 warps (2Mx4N), warp tile 64x32 (4x4 m16n8k8).
// Smem: A/B tiles [128][40] floats, double buffered (81920 B) + 1KB bias.
// k-permutation: logical k=2*tig placed at fragment slot tig, 2*tig+1 at
// slot tig+4, identically in A and B -> dot product unchanged, both
// fragments load as one float2 (LDS.64) each.
// ---------------------------------------------------------------------------
#define APITCH 40
#define TILE_BYTES (128 * APITCH * 4)            // 20480
#define SMEM_CONV (4 * TILE_BYTES + 1024)        // 82944

__global__ __launch_bounds__(256, 2)
void conv3x3_mma(const float* __restrict__ in,
                 const float* __restrict__ wT,    // [256][2304] tf32
                 const float* __restrict__ bias,
                 float* __restrict__ out)
{
    extern __shared__ float smem[];
    const uint32_t sb = smem_u32(smem);
    float* bias_s = smem + 4 * 128 * APITCH;

    const int t = threadIdx.x, wid = t >> 5, lane = t & 31;
    const int g = lane >> 2, tig = lane & 3;
    const int m0 = blockIdx.x * 128;
    const int n0 = blockIdx.y * 128;
    const int warpM = (wid & 1) * 64;
    const int warpN = (wid >> 1) * 32;

    if (t < 32) ((float4*)bias_s)[t] = ((const float4*)(bias + n0))[t];

    // global->smem load mappings (per thread: 4 A rows + 4 B rows, 16B each)
    const int cq4 = (t & 7) * 4;                 // k-word within 32
    int ahh[4], aww[4]; long abase[4];
    uint32_t adst[4], bdst[4];
    const float* bsrc[4];
#pragma unroll
    for (int s = 0; s < 4; ++s) {
        int row = (t >> 3) + s * 32;             // 0..127
        int m = m0 + row;
        int n = m / 196;
        int pp = m - n * 196;
        int hh = pp / 14;
        ahh[s] = hh; aww[s] = pp - hh * 14;
        abase[s] = (long)n * 50176 + cq4;
        adst[s] = sb + (row * APITCH + cq4) * 4;
        bsrc[s] = wT + (long)(n0 + row) * KTOT + cq4; // row as co within n0 slab
        bdst[s] = sb + 2 * TILE_BYTES + (row * APITCH + cq4) * 4;
    }

    float c[4][4][4];
#pragma unroll
    for (int i = 0; i < 4; ++i)
#pragma unroll
        for (int j = 0; j < 4; ++j)
#pragma unroll
            for (int q = 0; q < 4; ++q) c[i][j][q] = 0.f;

    auto load_tile = [&](int kt, int p) {
        const int kq = kt >> 3, ci0 = (kt & 7) << 5;
        const int kh = kq / 3, kw = kq - kh * 3;
        const uint32_t off = p * TILE_BYTES;
#pragma unroll
        for (int s = 0; s < 4; ++s) {
            int ih = ahh[s] + kh - 1, iw = aww[s] + kw - 1;
            bool ok = ((unsigned)ih < 14u) & ((unsigned)iw < 14u);
            int ihc = ok ? ih : 0, iwc = ok ? iw : 0;
            cp16(adst[s] + off, in + abase[s] + (ihc * 14 + iwc) * 256 + ci0,
                 ok ? 16u : 0u);
        }
#pragma unroll
        for (int s = 0; s < 4; ++s)
            cp16(bdst[s] + off, bsrc[s] + kt * 32, 16u);
        asm volatile("cp.async.commit_group;" ::: "memory");
    };

    load_tile(0, 0);

    for (int kt = 0; kt < 72; ++kt) {
        const int p = kt & 1;
        if (kt < 71) {
            load_tile(kt + 1, p ^ 1);
            asm volatile("cp.async.wait_group 1;" ::: "memory");
        } else {
            asm volatile("cp.async.wait_group 0;" ::: "memory");
        }
        __syncthreads();

        const float* As = smem + p * (TILE_BYTES / 4);
        const float* Bs = smem + (2 + p) * (TILE_BYTES / 4);
#pragma unroll
        for (int ks = 0; ks < 4; ++ks) {
            const int kb = ks * 8 + tig * 2;
            uint32_t a[4][4], bf[4][2];
#pragma unroll
            for (int i = 0; i < 4; ++i) {
                float2 v0 = *(const float2*)&As[(warpM + i * 16 + g) * APITCH + kb];
                float2 v1 = *(const float2*)&As[(warpM + i * 16 + g + 8) * APITCH + kb];
                a[i][0] = __float_as_uint(v0.x); a[i][2] = __float_as_uint(v0.y);
                a[i][1] = __float_as_uint(v1.x); a[i][3] = __float_as_uint(v1.y);
            }
#pragma unroll
            for (int j = 0; j < 4; ++j) {
                float2 v = *(const float2*)&Bs[(warpN + j * 8 + g) * APITCH + kb];
                bf[j][0] = __float_as_uint(v.x); bf[j][1] = __float_as_uint(v.y);
            }
#pragma unroll
            for (int i = 0; i < 4; ++i)
#pragma unroll
                for (int j = 0; j < 4; ++j)
                    mma_tf32(c[i][j], a[i], bf[j]);
        }
        __syncthreads();
    }

    // epilogue: bias + relu + tf32 round, float2 stores
#pragma unroll
    for (int j = 0; j < 4; ++j) {
        const int col = warpN + j * 8 + tig * 2;
        const float b0 = bias_s[col], b1 = bias_s[col + 1];
#pragma unroll
        for (int i = 0; i < 4; ++i) {
            long r0 = m0 + warpM + i * 16 + g;
            float2 o0, o1;
            o0.x = tf32r(fmaxf(c[i][j][0] + b0, 0.f));
            o0.y = tf32r(fmaxf(c[i][j][1] + b1, 0.f));
            o1.x = tf32r(fmaxf(c[i][j][2] + b0, 0.f));
            o1.y = tf32r(fmaxf(c[i][j][3] + b1, 0.f));
            *(float2*)&out[(r0 << 8) + n0 + col]       = o0;
            *(float2*)&out[((r0 + 8) << 8) + n0 + col] = o1;
        }
    }
}

// ---------------------------------------------------------------------------
// Fused deconv(2x2,s2,VALID)+relu + 1x1 mask conv (unchanged: known-correct)
// ---------------------------------------------------------------------------
#define ZPITCH 260

__global__ __launch_bounds__(256)
void deconv_mask_kernel(const float* __restrict__ y,
                        const float* __restrict__ Wt,
                        const float* __restrict__ bt,
                        const float* __restrict__ Wm,
                        const float* __restrict__ bm,
                        float* __restrict__ out)
{
    extern __shared__ float sm[];
    float* As  = sm;
    float* Bs  = As + 16 * 68;
    float* zs  = Bs + 16 * 256;
    float* wms = zs + 64 * ZPITCH;

    const int t  = threadIdx.x;
    const int m0 = blockIdx.x * 64;
    const int ab = blockIdx.y;
    const int a  = ab >> 1, b = ab & 1;
    const float* wbase = Wt + (3 - ab) * 256 * 256;   // Wt[1-a,1-b]

    for (int i = t * 4; i < 256 * 80; i += 256 * 4)
        *(float4*)&wms[i] = *(const float4*)&Wm[i];

    const int rA = t >> 2;
    const int c4 = (t & 3) * 4;
    const int ty = t >> 5;
    const int tx = t & 31;

    float acc[8][8];
#pragma unroll
    for (int i = 0; i < 8; ++i)
#pragma unroll
        for (int j = 0; j < 8; ++j) acc[i][j] = 0.f;

    for (int kc = 0; kc < 16; ++kc) {
        float4 av = *(const float4*)&y[((m0 + rA) << 8) + kc * 16 + c4];
        As[(c4 + 0) * 68 + rA] = av.x;
        As[(c4 + 1) * 68 + rA] = av.y;
        As[(c4 + 2) * 68 + rA] = av.z;
        As[(c4 + 3) * 68 + rA] = av.w;
#pragma unroll
        for (int j = 0; j < 4; ++j) {
            int v  = t + j * 256;
            int kr = v >> 6;
            int cb = (v & 63) * 4;
            *(float4*)&Bs[kr * 256 + cb] =
                *(const float4*)&wbase[(kc * 16 + kr) * 256 + cb];
        }
        __syncthreads();
#pragma unroll
        for (int kk = 0; kk < 16; ++kk) {
            float af[8], bf[8];
            *(float4*)&af[0] = *(const float4*)&As[kk * 68 + ty * 8];
            *(float4*)&af[4] = *(const float4*)&As[kk * 68 + ty * 8 + 4];
            *(float4*)&bf[0] = *(const float4*)&Bs[kk * 256 + tx * 8];
            *(float4*)&bf[4] = *(const float4*)&Bs[kk * 256 + tx * 8 + 4];
#pragma unroll
            for (int i = 0; i < 8; ++i)
#pragma unroll
                for (int j = 0; j < 8; ++j)
                    acc[i][j] += af[i] * bf[j];
        }
        __syncthreads();
    }

    float bvv[8];
#pragma unroll
    for (int j = 0; j < 8; ++j) bvv[j] = bt[tx * 8 + j];
#pragma unroll
    for (int i = 0; i < 8; ++i) {
        int r = ty * 8 + i;
        float4 z0, z1;
        z0.x = fmaxf(acc[i][0] + bvv[0], 0.f);
        z0.y = fmaxf(acc[i][1] + bvv[1], 0.f);
        z0.z = fmaxf(acc[i][2] + bvv[2], 0.f);
        z0.w = fmaxf(acc[i][3] + bvv[3], 0.f);
        z1.x = fmaxf(acc[i][4] + bvv[4], 0.f);
        z1.y = fmaxf(acc[i][5] + bvv[5], 0.f);
        z1.z = fmaxf(acc[i][6] + bvv[6], 0.f);
        z1.w = fmaxf(acc[i][7] + bvv[7], 0.f);
        *(float4*)&zs[r * ZPITCH + tx * 8]     = z0;
        *(float4*)&zs[r * ZPITCH + tx * 8 + 4] = z1;
    }
    __syncthreads();

    const int rg = (t >> 4) * 4;
    const int cg = (t & 15) * 5;
    float oacc[4][5];
#pragma unroll
    for (int rr = 0; rr < 4; ++rr)
#pragma unroll
        for (int cc = 0; cc < 5; ++cc) oacc[rr][cc] = bm[cg + cc];

    for (int co = 0; co < 256; ++co) {
        float zv[4], wv[5];
#pragma unroll
        for (int rr = 0; rr < 4; ++rr) zv[rr] = zs[(rg + rr) * ZPITCH + co];
#pragma unroll
        for (int cc = 0; cc < 5; ++cc) wv[cc] = wms[co * 80 + cg + cc];
#pragma unroll
        for (int rr = 0; rr < 4; ++rr)
#pragma unroll
            for (int cc = 0; cc < 5; ++cc)
                oacc[rr][cc] += zv[rr] * wv[cc];
    }

#pragma unroll
    for (int rr = 0; rr < 4; ++rr) {
        int m  = m0 + rg + rr;
        int n  = m / 196;
        int p  = m - n * 196;
        int ii = p / 14;
        int jj = p - ii * 14;
        int oh = ii * 2 + a;
        int ow = jj * 2 + b;
        float* op = &out[((n * 28 + oh) * 28 + ow) * 80 + cg];
#pragma unroll
        for (int cc = 0; cc < 5; ++cc) op[cc] = oacc[rr][cc];
    }
}

// ---------------------------------------------------------------------------
extern "C" void kernel_launch(void* const* d_in, const int* in_sizes, int n_in,
                              void* d_out, int out_size)
{
    const float* x  = (const float*)d_in[0];
    const float* Wc = (const float*)d_in[1];
    const float* bc = (const float*)d_in[2];
    const float* Wt = (const float*)d_in[3];
    const float* bt = (const float*)d_in[4];
    const float* Wm = (const float*)d_in[5];
    const float* bm = (const float*)d_in[6];
    float* out = (float*)d_out;

    float *b0, *b1, *wT;
    cudaGetSymbolAddress((void**)&b0, g_buf0);
    cudaGetSymbolAddress((void**)&b1, g_buf1);
    cudaGetSymbolAddress((void**)&wT, g_wT);

    cudaFuncSetAttribute(conv3x3_mma,
                         cudaFuncAttributeMaxDynamicSharedMemorySize, SMEM_CONV);
    const size_t smem_deconv =
        (16 * 68 + 16 * 256 + 64 * ZPITCH + 256 * 80) * sizeof(float);
    cudaFuncSetAttribute(deconv_mask_kernel,
                         cudaFuncAttributeMaxDynamicSharedMemorySize,
                         (int)smem_deconv);

    // prep: tf32-round x into b0; transpose+round weights
    round_tf32_kernel<<<(M_TOT * 256) / (256 * 4), 256>>>(x, b0);
    transpose_w<<<dim3(64, 9, 4), 256>>>(Wc, wT);

    dim3 cgrid(1568, 2);
    conv3x3_mma<<<cgrid, 256, SMEM_CONV>>>(b0, wT + 0L * WLSTRIDE, bc + 0,   b1);
    conv3x3_mma<<<cgrid, 256, SMEM_CONV>>>(b1, wT + 1L * WLSTRIDE, bc + 256, b0);
    conv3x3_mma<<<cgrid, 256, SMEM_CONV>>>(b0, wT + 2L * WLSTRIDE, bc + 512, b1);
    conv3x3_mma<<<cgrid, 256, SMEM_CONV>>>(b1, wT + 3L * WLSTRIDE, bc + 768, b0);

    dim3 dgrid(M_TOT / 64, 4);
    deconv_mask_kernel<<<dgrid, 256, smem_deconv>>>(b0, Wt, bt, Wm, bm, out);
}

// round 6
// speedup vs baseline: 4.0988x; 2.3330x over previous
#include <cuda_runtime.h>
#include <cstdint>

#define NROI 1024
#define M_TOT (NROI * 196)          // 200704
#define KTOT  2304
#define WLSTRIDE (256 * KTOT)

// Device-global scratch (allocation-free per harness rules)
__device__ float g_buf0[M_TOT * 256];
__device__ float g_buf1[M_TOT * 256];
__device__ float g_wT[4 * 256 * KTOT];     // conv weights [layer][co][k], tf32
__device__ float g_wdT[4 * 256 * 256];     // deconv weights [parity][co][ci], tf32
__device__ float g_wmT[80 * 256];          // mask weights [cls][ci], tf32
__device__ float g_zbuf[4L * M_TOT * 256]; // deconv output, parity-major (822 MB)

// ---------------------------------------------------------------------------
__device__ __forceinline__ uint32_t smem_u32(const void* p) {
    uint32_t a;
    asm("{ .reg .u64 t; cvta.to.shared.u64 t, %1; cvt.u32.u64 %0, t; }"
        : "=r"(a) : "l"(p));
    return a;
}
__device__ __forceinline__ float tf32r(float x) {
    float o; asm("cvt.rna.tf32.f32 %0, %1;" : "=f"(o) : "f"(x)); return o;
}
__device__ __forceinline__ void cp16(uint32_t dst, const void* src, uint32_t bytes) {
    asm volatile("cp.async.cg.shared.global [%0], [%1], 16, %2;"
                 :: "r"(dst), "l"(src), "r"(bytes) : "memory");
}
__device__ __forceinline__ void mma_tf32(float c[4], const uint32_t a[4],
                                         const uint32_t b[2]) {
    asm volatile(
        "mma.sync.aligned.m16n8k8.row.col.f32.tf32.tf32.f32 "
        "{%0,%1,%2,%3}, {%4,%5,%6,%7}, {%8,%9}, {%0,%1,%2,%3};"
        : "+f"(c[0]), "+f"(c[1]), "+f"(c[2]), "+f"(c[3])
        : "r"(a[0]), "r"(a[1]), "r"(a[2]), "r"(a[3]), "r"(b[0]), "r"(b[1]));
}

// ---------------------------------------------------------------------------
// Prep kernels
// ---------------------------------------------------------------------------
__global__ __launch_bounds__(256)
void round_tf32_kernel(const float* __restrict__ in, float* __restrict__ out)
{
    int i = (blockIdx.x * 256 + threadIdx.x) * 4;
    float4 v = *(const float4*)(in + i);
    v.x = tf32r(v.x); v.y = tf32r(v.y); v.z = tf32r(v.z); v.w = tf32r(v.w);
    *(float4*)(out + i) = v;
}

__global__ __launch_bounds__(256)
void transpose_w(const float* __restrict__ Wc, float* __restrict__ wT)
{
    __shared__ float ts[32][33];
    const int l  = blockIdx.z;
    const int kq = blockIdx.y;
    const int ci0 = (blockIdx.x >> 3) * 32;
    const int co0 = (blockIdx.x & 7) * 32;
    const int tx = threadIdx.x & 31, ty = threadIdx.x >> 5;
#pragma unroll
    for (int i = ty; i < 32; i += 8)
        ts[i][tx] = tf32r(Wc[((l * 9 + kq) * 256 + ci0 + i) * 256 + co0 + tx]);
    __syncthreads();
#pragma unroll
    for (int i = ty; i < 32; i += 8)
        wT[(l * 256 + co0 + i) * KTOT + kq * 256 + ci0 + tx] = ts[tx][i];
}

// wdT[ab][co][ci] = tf32(Wt[1-a][1-b][ci][co])  (parity map proven in R1)
__global__ __launch_bounds__(256)
void transpose_wd(const float* __restrict__ Wt, float* __restrict__ wdT)
{
    __shared__ float ts[32][33];
    const int ab  = blockIdx.z;
    const int ci0 = (blockIdx.x >> 3) * 32;
    const int co0 = (blockIdx.x & 7) * 32;
    const int tx = threadIdx.x & 31, ty = threadIdx.x >> 5;
    const float* src = Wt + (3 - ab) * 65536;
#pragma unroll
    for (int i = ty; i < 32; i += 8)
        ts[i][tx] = tf32r(src[(ci0 + i) * 256 + co0 + tx]);
    __syncthreads();
#pragma unroll
    for (int i = ty; i < 32; i += 8)
        wdT[ab * 65536 + (co0 + i) * 256 + ci0 + tx] = ts[tx][i];
}

// wmT[cls][ci] = tf32(Wm[ci][cls])
__global__ __launch_bounds__(256)
void transpose_wm(const float* __restrict__ Wm, float* __restrict__ wmT)
{
    int i = blockIdx.x * 256 + threadIdx.x;        // 0..20479
    if (i < 80 * 256) {
        int cls = i >> 8, ci = i & 255;
        wmT[i] = tf32r(Wm[ci * 80 + cls]);
    }
}

// ---------------------------------------------------------------------------
// Conv 3x3 SAME (256->256) + bias + ReLU via mma.sync tf32 (unchanged, R5 pass)
// ---------------------------------------------------------------------------
#define APITCH 40
#define TILE_BYTES (128 * APITCH * 4)            // 20480
#define SMEM_CONV (4 * TILE_BYTES + 1024)        // 82944

__global__ __launch_bounds__(256, 2)
void conv3x3_mma(const float* __restrict__ in,
                 const float* __restrict__ wT,
                 const float* __restrict__ bias,
                 float* __restrict__ out)
{
    extern __shared__ float smem[];
    const uint32_t sb = smem_u32(smem);
    float* bias_s = smem + 4 * 128 * APITCH;

    const int t = threadIdx.x, wid = t >> 5, lane = t & 31;
    const int g = lane >> 2, tig = lane & 3;
    const int m0 = blockIdx.x * 128;
    const int n0 = blockIdx.y * 128;
    const int warpM = (wid & 1) * 64;
    const int warpN = (wid >> 1) * 32;

    if (t < 32) ((float4*)bias_s)[t] = ((const float4*)(bias + n0))[t];

    const int cq4 = (t & 7) * 4;
    int ahh[4], aww[4]; long abase[4];
    uint32_t adst[4], bdst[4];
    const float* bsrc[4];
#pragma unroll
    for (int s = 0; s < 4; ++s) {
        int row = (t >> 3) + s * 32;
        int m = m0 + row;
        int n = m / 196;
        int pp = m - n * 196;
        int hh = pp / 14;
        ahh[s] = hh; aww[s] = pp - hh * 14;
        abase[s] = (long)n * 50176 + cq4;
        adst[s] = sb + (row * APITCH + cq4) * 4;
        bsrc[s] = wT + (long)(n0 + row) * KTOT + cq4;
        bdst[s] = sb + 2 * TILE_BYTES + (row * APITCH + cq4) * 4;
    }

    float c[4][4][4];
#pragma unroll
    for (int i = 0; i < 4; ++i)
#pragma unroll
        for (int j = 0; j < 4; ++j)
#pragma unroll
            for (int q = 0; q < 4; ++q) c[i][j][q] = 0.f;

    auto load_tile = [&](int kt, int p) {
        const int kq = kt >> 3, ci0 = (kt & 7) << 5;
        const int kh = kq / 3, kw = kq - kh * 3;
        const uint32_t off = p * TILE_BYTES;
#pragma unroll
        for (int s = 0; s < 4; ++s) {
            int ih = ahh[s] + kh - 1, iw = aww[s] + kw - 1;
            bool ok = ((unsigned)ih < 14u) & ((unsigned)iw < 14u);
            int ihc = ok ? ih : 0, iwc = ok ? iw : 0;
            cp16(adst[s] + off, in + abase[s] + (ihc * 14 + iwc) * 256 + ci0,
                 ok ? 16u : 0u);
        }
#pragma unroll
        for (int s = 0; s < 4; ++s)
            cp16(bdst[s] + off, bsrc[s] + kt * 32, 16u);
        asm volatile("cp.async.commit_group;" ::: "memory");
    };

    load_tile(0, 0);

    for (int kt = 0; kt < 72; ++kt) {
        const int p = kt & 1;
        if (kt < 71) {
            load_tile(kt + 1, p ^ 1);
            asm volatile("cp.async.wait_group 1;" ::: "memory");
        } else {
            asm volatile("cp.async.wait_group 0;" ::: "memory");
        }
        __syncthreads();

        const float* As = smem + p * (TILE_BYTES / 4);
        const float* Bs = smem + (2 + p) * (TILE_BYTES / 4);
#pragma unroll
        for (int ks = 0; ks < 4; ++ks) {
            const int kb = ks * 8 + tig * 2;
            uint32_t a[4][4], bf[4][2];
#pragma unroll
            for (int i = 0; i < 4; ++i) {
                float2 v0 = *(const float2*)&As[(warpM + i * 16 + g) * APITCH + kb];
                float2 v1 = *(const float2*)&As[(warpM + i * 16 + g + 8) * APITCH + kb];
                a[i][0] = __float_as_uint(v0.x); a[i][2] = __float_as_uint(v0.y);
                a[i][1] = __float_as_uint(v1.x); a[i][3] = __float_as_uint(v1.y);
            }
#pragma unroll
            for (int j = 0; j < 4; ++j) {
                float2 v = *(const float2*)&Bs[(warpN + j * 8 + g) * APITCH + kb];
                bf[j][0] = __float_as_uint(v.x); bf[j][1] = __float_as_uint(v.y);
            }
#pragma unroll
            for (int i = 0; i < 4; ++i)
#pragma unroll
                for (int j = 0; j < 4; ++j)
                    mma_tf32(c[i][j], a[i], bf[j]);
        }
        __syncthreads();
    }

#pragma unroll
    for (int j = 0; j < 4; ++j) {
        const int col = warpN + j * 8 + tig * 2;
        const float b0 = bias_s[col], b1 = bias_s[col + 1];
#pragma unroll
        for (int i = 0; i < 4; ++i) {
            long r0 = m0 + warpM + i * 16 + g;
            float2 o0, o1;
            o0.x = tf32r(fmaxf(c[i][j][0] + b0, 0.f));
            o0.y = tf32r(fmaxf(c[i][j][1] + b1, 0.f));
            o1.x = tf32r(fmaxf(c[i][j][2] + b0, 0.f));
            o1.y = tf32r(fmaxf(c[i][j][3] + b1, 0.f));
            *(float2*)&out[(r0 << 8) + n0 + col]       = o0;
            *(float2*)&out[((r0 + 8) << 8) + n0 + col] = o1;
        }
    }
}

// ---------------------------------------------------------------------------
// D1: deconv as GEMM per parity: z[ab][m][co] = relu(y[m][:] . wdT[ab][co][:] + bt)
// Same structure as conv3x3_mma, K=256 (8 k-tiles), dense A, no padding.
// ---------------------------------------------------------------------------
__global__ __launch_bounds__(256, 2)
void deconv_gemm(const float* __restrict__ y,
                 const float* __restrict__ wdT,
                 const float* __restrict__ bt,
                 float* __restrict__ z)
{
    extern __shared__ float smem[];
    const uint32_t sb = smem_u32(smem);
    float* bias_s = smem + 4 * 128 * APITCH;

    const int t = threadIdx.x, wid = t >> 5, lane = t & 31;
    const int g = lane >> 2, tig = lane & 3;
    const int m0 = blockIdx.x * 128;
    const int n0 = blockIdx.y * 128;
    const int ab = blockIdx.z;
    const int warpM = (wid & 1) * 64;
    const int warpN = (wid >> 1) * 32;

    if (t < 32) ((float4*)bias_s)[t] = ((const float4*)(bt + n0))[t];

    const int cq4 = (t & 7) * 4;
    uint32_t adst[4], bdst[4];
    const float* asrc[4];
    const float* bsrc[4];
#pragma unroll
    for (int s = 0; s < 4; ++s) {
        int row = (t >> 3) + s * 32;
        asrc[s] = y + (long)(m0 + row) * 256 + cq4;
        adst[s] = sb + (row * APITCH + cq4) * 4;
        bsrc[s] = wdT + ab * 65536 + (n0 + row) * 256 + cq4;
        bdst[s] = sb + 2 * TILE_BYTES + (row * APITCH + cq4) * 4;
    }

    float c[4][4][4];
#pragma unroll
    for (int i = 0; i < 4; ++i)
#pragma unroll
        for (int j = 0; j < 4; ++j)
#pragma unroll
            for (int q = 0; q < 4; ++q) c[i][j][q] = 0.f;

    auto load_tile = [&](int kt, int p) {
        const uint32_t off = p * TILE_BYTES;
#pragma unroll
        for (int s = 0; s < 4; ++s) cp16(adst[s] + off, asrc[s] + kt * 32, 16u);
#pragma unroll
        for (int s = 0; s < 4; ++s) cp16(bdst[s] + off, bsrc[s] + kt * 32, 16u);
        asm volatile("cp.async.commit_group;" ::: "memory");
    };

    load_tile(0, 0);

    for (int kt = 0; kt < 8; ++kt) {
        const int p = kt & 1;
        if (kt < 7) {
            load_tile(kt + 1, p ^ 1);
            asm volatile("cp.async.wait_group 1;" ::: "memory");
        } else {
            asm volatile("cp.async.wait_group 0;" ::: "memory");
        }
        __syncthreads();

        const float* As = smem + p * (TILE_BYTES / 4);
        const float* Bs = smem + (2 + p) * (TILE_BYTES / 4);
#pragma unroll
        for (int ks = 0; ks < 4; ++ks) {
            const int kb = ks * 8 + tig * 2;
            uint32_t a[4][4], bf[4][2];
#pragma unroll
            for (int i = 0; i < 4; ++i) {
                float2 v0 = *(const float2*)&As[(warpM + i * 16 + g) * APITCH + kb];
                float2 v1 = *(const float2*)&As[(warpM + i * 16 + g + 8) * APITCH + kb];
                a[i][0] = __float_as_uint(v0.x); a[i][2] = __float_as_uint(v0.y);
                a[i][1] = __float_as_uint(v1.x); a[i][3] = __float_as_uint(v1.y);
            }
#pragma unroll
            for (int j = 0; j < 4; ++j) {
                float2 v = *(const float2*)&Bs[(warpN + j * 8 + g) * APITCH + kb];
                bf[j][0] = __float_as_uint(v.x); bf[j][1] = __float_as_uint(v.y);
            }
#pragma unroll
            for (int i = 0; i < 4; ++i)
#pragma unroll
                for (int j = 0; j < 4; ++j)
                    mma_tf32(c[i][j], a[i], bf[j]);
        }
        __syncthreads();
    }

    float* zout = z + (long)ab * M_TOT * 256;
#pragma unroll
    for (int j = 0; j < 4; ++j) {
        const int col = warpN + j * 8 + tig * 2;
        const float b0 = bias_s[col], b1 = bias_s[col + 1];
#pragma unroll
        for (int i = 0; i < 4; ++i) {
            long r0 = m0 + warpM + i * 16 + g;
            float2 o0, o1;
            o0.x = tf32r(fmaxf(c[i][j][0] + b0, 0.f));
            o0.y = tf32r(fmaxf(c[i][j][1] + b1, 0.f));
            o1.x = tf32r(fmaxf(c[i][j][2] + b0, 0.f));
            o1.y = tf32r(fmaxf(c[i][j][3] + b1, 0.f));
            *(float2*)&zout[(r0 << 8) + n0 + col]       = o0;
            *(float2*)&zout[((r0 + 8) << 8) + n0 + col] = o1;
        }
    }
}

// ---------------------------------------------------------------------------
// D2: mask GEMM: out = z @ WmT^T + bm. M=802816, N=80, K=256.
// BM=128, 8 warps each 16x80 (10 n8 tiles), BK=32 double-buffered.
// Epilogue scatters rows to [n,28,28,80] via the parity map.
// ---------------------------------------------------------------------------
#define D2_ASIZE (128 * APITCH)     // 5120 floats
#define D2_BSIZE (80 * APITCH)      // 3200 floats
#define SMEM_D2  ((2 * D2_ASIZE + 2 * D2_BSIZE) * 4)   // 66560 B

__global__ __launch_bounds__(256, 2)
void mask_gemm(const float* __restrict__ z,
               const float* __restrict__ wmT,
               const float* __restrict__ bm,
               float* __restrict__ out)
{
    extern __shared__ float smem[];
    const uint32_t sb = smem_u32(smem);
    const int t = threadIdx.x, wid = t >> 5, lane = t & 31;
    const int g = lane >> 2, tig = lane & 3;
    const long m0 = (long)blockIdx.x * 128;
    const int ab = (int)(m0 / M_TOT);            // uniform per CTA (M_TOT%128==0)
    const int aa = ab >> 1, bb = ab & 1;
    const int pix0 = (int)(m0 - (long)ab * M_TOT);

    const int cq4 = (t & 7) * 4;
    uint32_t adst[4]; const float* asrc[4];
#pragma unroll
    for (int s = 0; s < 4; ++s) {
        int row = (t >> 3) + s * 32;
        asrc[s] = z + (m0 + row) * 256 + cq4;
        adst[s] = sb + (row * APITCH + cq4) * 4;
    }

    float c[10][4];
#pragma unroll
    for (int j = 0; j < 10; ++j)
#pragma unroll
        for (int q = 0; q < 4; ++q) c[j][q] = 0.f;

    auto load_tile = [&](int kt, int p) {
#pragma unroll
        for (int s = 0; s < 4; ++s)
            cp16(adst[s] + p * (D2_ASIZE * 4), asrc[s] + kt * 32, 16u);
        for (int ch = t; ch < 640; ch += 256) {
            int row = ch >> 3, k4 = (ch & 7) * 4;
            cp16(sb + (2 * D2_ASIZE + p * D2_BSIZE + row * APITCH + k4) * 4,
                 wmT + row * 256 + kt * 32 + k4, 16u);
        }
        asm volatile("cp.async.commit_group;" ::: "memory");
    };

    load_tile(0, 0);

    for (int kt = 0; kt < 8; ++kt) {
        const int p = kt & 1;
        if (kt < 7) {
            load_tile(kt + 1, p ^ 1);
            asm volatile("cp.async.wait_group 1;" ::: "memory");
        } else {
            asm volatile("cp.async.wait_group 0;" ::: "memory");
        }
        __syncthreads();

        const float* As = smem + p * D2_ASIZE;
        const float* Bs = smem + 2 * D2_ASIZE + p * D2_BSIZE;
#pragma unroll
        for (int ks = 0; ks < 4; ++ks) {
            const int kb = ks * 8 + tig * 2;
            uint32_t a[4];
            float2 v0 = *(const float2*)&As[(wid * 16 + g) * APITCH + kb];
            float2 v1 = *(const float2*)&As[(wid * 16 + g + 8) * APITCH + kb];
            a[0] = __float_as_uint(v0.x); a[2] = __float_as_uint(v0.y);
            a[1] = __float_as_uint(v1.x); a[3] = __float_as_uint(v1.y);
#pragma unroll
            for (int j = 0; j < 10; ++j) {
                float2 v = *(const float2*)&Bs[(j * 8 + g) * APITCH + kb];
                uint32_t bf[2] = {__float_as_uint(v.x), __float_as_uint(v.y)};
                mma_tf32(c[j], a, bf);
            }
        }
        __syncthreads();
    }

    // epilogue: + bm, scatter to [n,28,28,80]
    float bmv[10][2];
#pragma unroll
    for (int j = 0; j < 10; ++j) {
        int col = j * 8 + tig * 2;
        bmv[j][0] = bm[col]; bmv[j][1] = bm[col + 1];
    }

    int pixA = pix0 + wid * 16 + g;
    int pixB = pixA + 8;
    int nA = pixA / 196, pA = pixA - nA * 196, iiA = pA / 14, jjA = pA - iiA * 14;
    int nB = pixB / 196, pB = pixB - nB * 196, iiB = pB / 14, jjB = pB - iiB * 14;
    float* opA = out + ((long)(nA * 28 + iiA * 2 + aa) * 28 + jjA * 2 + bb) * 80;
    float* opB = out + ((long)(nB * 28 + iiB * 2 + aa) * 28 + jjB * 2 + bb) * 80;

#pragma unroll
    for (int j = 0; j < 10; ++j) {
        int col = j * 8 + tig * 2;
        float2 oA = make_float2(c[j][0] + bmv[j][0], c[j][1] + bmv[j][1]);
        float2 oB = make_float2(c[j][2] + bmv[j][0], c[j][3] + bmv[j][1]);
        *(float2*)&opA[col] = oA;
        *(float2*)&opB[col] = oB;
    }
}

// ---------------------------------------------------------------------------
extern "C" void kernel_launch(void* const* d_in, const int* in_sizes, int n_in,
                              void* d_out, int out_size)
{
    const float* x  = (const float*)d_in[0];
    const float* Wc = (const float*)d_in[1];
    const float* bc = (const float*)d_in[2];
    const float* Wt = (const float*)d_in[3];
    const float* bt = (const float*)d_in[4];
    const float* Wm = (const float*)d_in[5];
    const float* bm = (const float*)d_in[6];
    float* out = (float*)d_out;

    float *b0, *b1, *wT, *wdT, *wmT, *zbuf;
    cudaGetSymbolAddress((void**)&b0,  g_buf0);
    cudaGetSymbolAddress((void**)&b1,  g_buf1);
    cudaGetSymbolAddress((void**)&wT,  g_wT);
    cudaGetSymbolAddress((void**)&wdT, g_wdT);
    cudaGetSymbolAddress((void**)&wmT, g_wmT);
    cudaGetSymbolAddress((void**)&zbuf, g_zbuf);

    cudaFuncSetAttribute(conv3x3_mma,
                         cudaFuncAttributeMaxDynamicSharedMemorySize, SMEM_CONV);
    cudaFuncSetAttribute(deconv_gemm,
                         cudaFuncAttributeMaxDynamicSharedMemorySize, SMEM_CONV);
    cudaFuncSetAttribute(mask_gemm,
                         cudaFuncAttributeMaxDynamicSharedMemorySize, SMEM_D2);

    // prep
    round_tf32_kernel<<<(M_TOT * 256) / (256 * 4), 256>>>(x, b0);
    transpose_w<<<dim3(64, 9, 4), 256>>>(Wc, wT);
    transpose_wd<<<dim3(64, 1, 4), 256>>>(Wt, wdT);
    transpose_wm<<<80, 256>>>(Wm, wmT);

    // conv chain
    dim3 cgrid(1568, 2);
    conv3x3_mma<<<cgrid, 256, SMEM_CONV>>>(b0, wT + 0L * WLSTRIDE, bc + 0,   b1);
    conv3x3_mma<<<cgrid, 256, SMEM_CONV>>>(b1, wT + 1L * WLSTRIDE, bc + 256, b0);
    conv3x3_mma<<<cgrid, 256, SMEM_CONV>>>(b0, wT + 2L * WLSTRIDE, bc + 512, b1);
    conv3x3_mma<<<cgrid, 256, SMEM_CONV>>>(b1, wT + 3L * WLSTRIDE, bc + 768, b0);

    // deconv (per parity) + mask
    deconv_gemm<<<dim3(1568, 2, 4), 256, SMEM_CONV>>>(b0, wdT, bt, zbuf);
    mask_gemm<<<4 * M_TOT / 128, 256, SMEM_D2>>>(zbuf, wmT, bm, out);
}